// round 6
// baseline (speedup 1.0000x reference)
#include <cuda_runtime.h>
#include <cuda_fp16.h>

// Problem constants (fixed shapes per reference setup_inputs)
#define BB    4
#define HH    352            // rows; 352 = 44 * 8
#define WW    1216           // cols; 1216 = 4 * 304, 304 = 16 * 19
#define PLANE (HH * WW)      // 428032
#define NPIX  (BB * PLANE)   // 1712128
#define NGRP  (NPIX / 4)     // 428032  (4-px groups), PLANE/4 = 107008
#define GPR   304            // groups per row

// Fused-prop tile geometry
#define TW 16                // tile width in groups (64 px)
#define TH 44                // tile height in rows
#define EW 18                // expanded width  (+1 group each side)
#define EH 48                // expanded height (+2 rows each side)
#define NHALO 160            // EH*EW - TH*TW = 864 - 704
#define SP 76                // smem row stride in floats (72 px + pad)

// Weight records: one 144-B record per 4-px group = 9 x uint4.
// uint4 j = { w1 px01, w2 px01, w1 px23, w2 px23 } (each 2 halves).
// Tap-major swizzle in 32-group blocks over the CANONICAL flat group id
//   g = b*(PLANE/4) + h*304 + gw :   idx(g,j) = (g>>5)*288 + j*32 + (g&31)
__device__ uint4 g_wrec[(size_t)NGRP * 9];   // 61.6 MB
__device__ float g_xa[NPIX];                 // 6.85 MB
__device__ float g_xb[NPIX];                 // 6.85 MB

static __device__ __forceinline__ size_t widx(int g, int j) {
    return (size_t)(g >> 5) * 288 + j * 32 + (g & 31);
}

// Apply the taps that touch window-row r (r = 0..4) to the 4 accumulators.
// Window cols 0..11 map to px gg*4-4 .. gg*4+7; output px i has center 4+i.
static __device__ __forceinline__ void apply_row(
    int r, const float xr[12], const uint4 rec[9], float acc[4])
{
    if (r >= 1 && r <= 3) {            // dilation-1 taps, dr = r-1
        int dr = r - 1;
#pragma unroll
        for (int dc = 0; dc < 3; dc++) {
            const uint4& R = rec[dr * 3 + dc];
            float2 a01 = __half22float2(*(const __half2*)&R.x);
            float2 a23 = __half22float2(*(const __half2*)&R.z);
            acc[0] += a01.x * xr[3 + dc];
            acc[1] += a01.y * xr[4 + dc];
            acc[2] += a23.x * xr[5 + dc];
            acc[3] += a23.y * xr[6 + dc];
        }
    }
    if ((r & 1) == 0) {                // dilation-2 taps, dr = r/2
        int dr = r >> 1;
#pragma unroll
        for (int dc = 0; dc < 3; dc++) {
            const uint4& R = rec[dr * 3 + dc];
            float2 b01 = __half22float2(*(const __half2*)&R.y);
            float2 b23 = __half22float2(*(const __half2*)&R.w);
            acc[0] += b01.x * xr[2 + 2 * dc];
            acc[1] += b01.y * xr[3 + 2 * dc];
            acc[2] += b23.x * xr[4 + 2 * dc];
            acc[3] += b23.y * xr[5 + 2 * dc];
        }
    }
}

// One propagation step for group (gh, gg) of one image, reading x from
// global memory (zero-padded), accumulating into acc[4]. Row-streamed to
// keep register pressure low.
static __device__ __forceinline__ void compute_group(
    const float* __restrict__ xbm, int gh, int gg, const uint4 rec[9],
    float acc[4])
{
    int w0 = gg * 4;
#pragma unroll
    for (int r = 0; r < 5; r++) {
        int hh = gh + r - 2;
        bool rok = (hh >= 0) && (hh < HH);
        const float* rowp = xbm + hh * WW;
        float xr[12];
#pragma unroll
        for (int q = 0; q < 3; q++) {
            int c0 = w0 + (q - 1) * 4;
            float4 v = make_float4(0.f, 0.f, 0.f, 0.f);
            if (rok && c0 >= 0 && c0 < WW)
                v = *(const float4*)(rowp + c0);
            xr[q * 4 + 0] = v.x;
            xr[q * 4 + 1] = v.y;
            xr[q * 4 + 2] = v.z;
            xr[q * 4 + 3] = v.w;
        }
        apply_row(r, xr, rec, acc);
    }
}

// ---------------------------------------------------------------------------
// prep: per-pixel 9-way softmax of guided1/guided2, scaled by fuse channels.
// Flat 1D: thread u handles 2 px = half of record g = u>>1. Grid exact.
// ---------------------------------------------------------------------------
__global__ __launch_bounds__(512) void prep_kernel(
    const float* __restrict__ g1,
    const float* __restrict__ g2,
    const float* __restrict__ fu,
    uint4* __restrict__ wrec)
{
    int u  = blockIdx.x * 512 + threadIdx.x;   // < 2*NGRP
    int g  = u >> 1;
    int tz = u & 1;
    int px = g * 4 + tz * 2;                   // flat pixel over (b,h,w)
    int b  = px / PLANE;
    int hw = px - b * PLANE;
    int base9 = b * 9 * PLANE + hw;
    int base2 = b * 2 * PLANE + hw;

    float a[9][2], c[9][2];
#pragma unroll
    for (int t = 0; t < 9; t++) {
        *(float2*)a[t] = *(const float2*)(g1 + base9 + t * PLANE);
        *(float2*)c[t] = *(const float2*)(g2 + base9 + t * PLANE);
    }
    float2 f1v = *(const float2*)(fu + base2);
    float2 f2v = *(const float2*)(fu + base2 + PLANE);
    float f1a[2] = {f1v.x, f1v.y};
    float f2a[2] = {f2v.x, f2v.y};

#pragma unroll
    for (int i = 0; i < 2; i++) {
        float m1 = a[0][i], m2 = c[0][i];
#pragma unroll
        for (int t = 1; t < 9; t++) {
            m1 = fmaxf(m1, a[t][i]);
            m2 = fmaxf(m2, c[t][i]);
        }
        float s1 = 0.f, s2 = 0.f;
#pragma unroll
        for (int t = 0; t < 9; t++) {
            float e1 = __expf(a[t][i] - m1); a[t][i] = e1; s1 += e1;
            float e2 = __expf(c[t][i] - m2); c[t][i] = e2; s2 += e2;
        }
        float r1 = f1a[i] / s1;
        float r2 = f2a[i] / s2;
#pragma unroll
        for (int t = 0; t < 9; t++) { a[t][i] *= r1; c[t][i] *= r2; }
    }

#pragma unroll
    for (int j = 0; j < 9; j++) {
        __half2 hw1 = __floats2half2_rn(a[j][0], a[j][1]);
        __half2 hw2 = __floats2half2_rn(c[j][0], c[j][1]);
        uint2 uu;
        uu.x = *(const unsigned int*)&hw1;
        uu.y = *(const unsigned int*)&hw2;
        ((uint2*)&wrec[widx(g, j)])[tz] = uu;
    }
}

// ---------------------------------------------------------------------------
// prop2: TWO fused propagation iterations.
// Stage 1: iter k on the expanded 48x18-group region -> smem. Halo groups
//   (160) done by threads 0..159 first; then EVERY thread does its own
//   group and KEEPS its rec[9] in registers.
// Stage 2: iter k+1 for the own group from smem, reusing the register recs.
// Each weight record is read from L2 exactly once per launch (1.23x per
// 2 iterations vs 2.0x unfused).
// ---------------------------------------------------------------------------
__global__ __launch_bounds__(704, 1) void prop2_kernel(
    const float* __restrict__ xin,
    const uint4* __restrict__ wrec,
    float* __restrict__ xout)
{
    __shared__ float xmid[EH * SP];            // 48 rows x 72 px (+pad)

    int tx = threadIdx.x;                      // 0..15 group-in-tile
    int ty = threadIdx.y;                      // 0..43 row-in-tile
    int tid = ty * TW + tx;
    int bx = blockIdx.x, by = blockIdx.y, b = blockIdx.z;
    int g0 = bx * TW, row0 = by * TH;
    const float* xbm = xin + b * PLANE;

    // ---- stage 1a: halo groups ----
    if (tid < NHALO) {
        int er, ec;
        if (tid < 36)       { er = tid / EW;              ec = tid % EW; }
        else if (tid < 72)  { int v = tid - 36; er = EH - 2 + v / EW; ec = v % EW; }
        else if (tid < 116) { er = 2 + (tid - 72);        ec = 0; }
        else                { er = 2 + (tid - 116);       ec = EW - 1; }
        int gh = row0 - 2 + er;
        int gg = g0 - 1 + ec;
        float out[4] = {0.f, 0.f, 0.f, 0.f};
        if (gh >= 0 && gh < HH && gg >= 0 && gg < GPR) {
            uint4 hrec[9];
            int hg = b * (PLANE / 4) + gh * GPR + gg;
#pragma unroll
            for (int j = 0; j < 9; j++)
                hrec[j] = __ldcg(&wrec[widx(hg, j)]);
            compute_group(xbm, gh, gg, hrec, out);
        }
        *(float4*)&xmid[er * SP + ec * 4] =
            make_float4(out[0], out[1], out[2], out[3]);
    }

    // ---- stage 1b: own group (rec kept in registers for stage 2) ----
    int gh = row0 + ty;
    int gg = g0 + tx;
    uint4 rec[9];
    {
        int g = b * (PLANE / 4) + gh * GPR + gg;
#pragma unroll
        for (int j = 0; j < 9; j++)
            rec[j] = __ldcg(&wrec[widx(g, j)]);
    }
    {
        float out[4] = {0.f, 0.f, 0.f, 0.f};
        compute_group(xbm, gh, gg, rec, out);
        *(float4*)&xmid[(ty + 2) * SP + (tx + 1) * 4] =
            make_float4(out[0], out[1], out[2], out[3]);
    }

    __syncthreads();

    // ---- stage 2: iter k+1 for the own group from smem ----
    // Own group lives at smem row ty+2, px (tx+1)*4. Its 5x12 window is
    // smem rows ty..ty+4, px cols tx*4 .. tx*4+11 (all in-range; stage 1
    // wrote zeros for out-of-image positions = correct zero padding).
    float acc[4] = {0.f, 0.f, 0.f, 0.f};
#pragma unroll
    for (int r = 0; r < 5; r++) {
        const float* rp = &xmid[(ty + r) * SP + tx * 4];
        float4 v0 = *(const float4*)rp;
        float4 v1 = *(const float4*)(rp + 4);
        float4 v2 = *(const float4*)(rp + 8);
        float xr[12] = {v0.x, v0.y, v0.z, v0.w,
                        v1.x, v1.y, v1.z, v1.w,
                        v2.x, v2.y, v2.z, v2.w};
        apply_row(r, xr, rec, acc);
    }

    *(float4*)(xout + b * PLANE + gh * WW + gg * 4) =
        make_float4(acc[0], acc[1], acc[2], acc[3]);
}

// ---------------------------------------------------------------------------
// Launcher: prep, then 4 fused double-iterations (8 total).
// ---------------------------------------------------------------------------
extern "C" void kernel_launch(void* const* d_in, const int* in_sizes, int n_in,
                              void* d_out, int out_size)
{
    const float* g1 = (const float*)d_in[0];
    const float* g2 = (const float*)d_in[1];
    const float* fu = (const float*)d_in[2];
    const float* x0 = (const float*)d_in[3];
    float* out = (float*)d_out;

    uint4* wrec;
    float *xa, *xb;
    cudaGetSymbolAddress((void**)&wrec, g_wrec);
    cudaGetSymbolAddress((void**)&xa, g_xa);
    cudaGetSymbolAddress((void**)&xb, g_xb);

    prep_kernel<<<2 * NGRP / 512, 512>>>(g1, g2, fu, wrec);

    dim3 pblk(TW, TH, 1);
    dim3 pgrd(GPR / TW, HH / TH, BB);     // (19, 8, 4)
    prop2_kernel<<<pgrd, pblk>>>(x0, wrec, xa);
    prop2_kernel<<<pgrd, pblk>>>(xa, wrec, xb);
    prop2_kernel<<<pgrd, pblk>>>(xb, wrec, xa);
    prop2_kernel<<<pgrd, pblk>>>(xa, wrec, out);
}

// round 7
// speedup vs baseline: 1.0038x; 1.0038x over previous
#include <cuda_runtime.h>
#include <cuda_fp16.h>

// Problem constants (fixed shapes per reference setup_inputs)
#define BB    4
#define HH    352            // rows; 352 = 16 * 22
#define WW    1216           // cols; 1216 = 4 * 304, 304 = 16 * 19
#define PLANE (HH * WW)      // 428032
#define NPIX  (BB * PLANE)   // 1712128
#define NGRP  (NPIX / 4)     // 428032  (4-px groups), PLANE/4 = 107008
#define GPR   304            // groups per row

// Fused-prop tile geometry: own tile 16 rows x 16 groups (256 threads,
// 1 group each); expanded stage-1 region 20 rows x 18 groups.
#define TW 16
#define TH 16
#define EW 18
#define EH 20
#define NHALO 104            // EH*EW - TH*TW = 360 - 256
#define SP 76                // smem row stride in floats (72 px + pad)

// Weight records: one 144-B record per 4-px group = 9 x uint4.
// uint4 j = { w1 px01, w2 px01, w1 px23, w2 px23 } (each 2 halves).
// Tap-major swizzle in 32-group blocks over the CANONICAL flat group id
//   g = b*(PLANE/4) + h*304 + gw :   idx(g,j) = (g>>5)*288 + j*32 + (g&31)
__device__ uint4 g_wrec[(size_t)NGRP * 9];   // 61.6 MB
__device__ float g_xa[NPIX];                 // 6.85 MB
__device__ float g_xb[NPIX];                 // 6.85 MB

static __device__ __forceinline__ size_t widx(int g, int j) {
    return (size_t)(g >> 5) * 288 + j * 32 + (g & 31);
}

// Apply the taps that touch window-row r (r = 0..4) to the 4 accumulators.
// Window cols 0..11 map to px gg*4-4 .. gg*4+7; output px i has center 4+i.
static __device__ __forceinline__ void apply_row(
    int r, const float xr[12], const uint4 rec[9], float acc[4])
{
    if (r >= 1 && r <= 3) {            // dilation-1 taps, dr = r-1
        int dr = r - 1;
#pragma unroll
        for (int dc = 0; dc < 3; dc++) {
            const uint4& R = rec[dr * 3 + dc];
            float2 a01 = __half22float2(*(const __half2*)&R.x);
            float2 a23 = __half22float2(*(const __half2*)&R.z);
            acc[0] += a01.x * xr[3 + dc];
            acc[1] += a01.y * xr[4 + dc];
            acc[2] += a23.x * xr[5 + dc];
            acc[3] += a23.y * xr[6 + dc];
        }
    }
    if ((r & 1) == 0) {                // dilation-2 taps, dr = r/2
        int dr = r >> 1;
#pragma unroll
        for (int dc = 0; dc < 3; dc++) {
            const uint4& R = rec[dr * 3 + dc];
            float2 b01 = __half22float2(*(const __half2*)&R.y);
            float2 b23 = __half22float2(*(const __half2*)&R.w);
            acc[0] += b01.x * xr[2 + 2 * dc];
            acc[1] += b01.y * xr[3 + 2 * dc];
            acc[2] += b23.x * xr[4 + 2 * dc];
            acc[3] += b23.y * xr[5 + 2 * dc];
        }
    }
}

// One propagation step for group (gh, gg) of one image, reading x from
// global memory (zero-padded), accumulating into acc[4]. Row-streamed.
static __device__ __forceinline__ void compute_group(
    const float* __restrict__ xbm, int gh, int gg, const uint4 rec[9],
    float acc[4])
{
    int w0 = gg * 4;
#pragma unroll
    for (int r = 0; r < 5; r++) {
        int hh = gh + r - 2;
        bool rok = (hh >= 0) && (hh < HH);
        const float* rowp = xbm + hh * WW;
        float xr[12];
#pragma unroll
        for (int q = 0; q < 3; q++) {
            int c0 = w0 + (q - 1) * 4;
            float4 v = make_float4(0.f, 0.f, 0.f, 0.f);
            if (rok && c0 >= 0 && c0 < WW)
                v = *(const float4*)(rowp + c0);
            xr[q * 4 + 0] = v.x;
            xr[q * 4 + 1] = v.y;
            xr[q * 4 + 2] = v.z;
            xr[q * 4 + 3] = v.w;
        }
        apply_row(r, xr, rec, acc);
    }
}

// ---------------------------------------------------------------------------
// prep: per-pixel 9-way softmax of guided1/guided2, scaled by fuse channels.
// Flat 1D: thread u handles 2 px = half of record g = u>>1. Grid exact.
// ---------------------------------------------------------------------------
__global__ __launch_bounds__(512) void prep_kernel(
    const float* __restrict__ g1,
    const float* __restrict__ g2,
    const float* __restrict__ fu,
    uint4* __restrict__ wrec)
{
    int u  = blockIdx.x * 512 + threadIdx.x;   // < 2*NGRP
    int g  = u >> 1;
    int tz = u & 1;
    int px = g * 4 + tz * 2;                   // flat pixel over (b,h,w)
    int b  = px / PLANE;
    int hw = px - b * PLANE;
    int base9 = b * 9 * PLANE + hw;
    int base2 = b * 2 * PLANE + hw;

    float a[9][2], c[9][2];
#pragma unroll
    for (int t = 0; t < 9; t++) {
        *(float2*)a[t] = *(const float2*)(g1 + base9 + t * PLANE);
        *(float2*)c[t] = *(const float2*)(g2 + base9 + t * PLANE);
    }
    float2 f1v = *(const float2*)(fu + base2);
    float2 f2v = *(const float2*)(fu + base2 + PLANE);
    float f1a[2] = {f1v.x, f1v.y};
    float f2a[2] = {f2v.x, f2v.y};

#pragma unroll
    for (int i = 0; i < 2; i++) {
        float m1 = a[0][i], m2 = c[0][i];
#pragma unroll
        for (int t = 1; t < 9; t++) {
            m1 = fmaxf(m1, a[t][i]);
            m2 = fmaxf(m2, c[t][i]);
        }
        float s1 = 0.f, s2 = 0.f;
#pragma unroll
        for (int t = 0; t < 9; t++) {
            float e1 = __expf(a[t][i] - m1); a[t][i] = e1; s1 += e1;
            float e2 = __expf(c[t][i] - m2); c[t][i] = e2; s2 += e2;
        }
        float r1 = f1a[i] / s1;
        float r2 = f2a[i] / s2;
#pragma unroll
        for (int t = 0; t < 9; t++) { a[t][i] *= r1; c[t][i] *= r2; }
    }

#pragma unroll
    for (int j = 0; j < 9; j++) {
        __half2 hw1 = __floats2half2_rn(a[j][0], a[j][1]);
        __half2 hw2 = __floats2half2_rn(c[j][0], c[j][1]);
        uint2 uu;
        uu.x = *(const unsigned int*)&hw1;
        uu.y = *(const unsigned int*)&hw2;
        ((uint2*)&wrec[widx(g, j)])[tz] = uu;
    }
}

// ---------------------------------------------------------------------------
// prop2: TWO fused propagation iterations, 256-thread blocks.
// Stage 1: iter k on expanded 20x18-group region -> smem. Threads 0..103
//   each do one halo group (rec discarded), then EVERY thread does its own
//   group keeping rec[9] in registers.
// Stage 2: iter k+1 for the own group from smem, reusing register recs.
// Weight reads per 2 iters = 360/256 = 1.41x single-iter (vs 2.0 unfused).
// Small blocks + reg cap -> 3 CTAs/SM so sync/halo stalls are overlapped.
// ---------------------------------------------------------------------------
__global__ __launch_bounds__(256, 3) void prop2_kernel(
    const float* __restrict__ xin,
    const uint4* __restrict__ wrec,
    float* __restrict__ xout)
{
    __shared__ float xmid[EH * SP];            // 20 rows x 72 px (+pad)

    int tx = threadIdx.x;                      // 0..15 group-in-tile
    int ty = threadIdx.y;                      // 0..15 row-in-tile
    int tid = ty * TW + tx;
    int bx = blockIdx.x, by = blockIdx.y, b = blockIdx.z;
    int g0 = bx * TW, row0 = by * TH;
    const float* xbm = xin + b * PLANE;

    // ---- stage 1a: halo groups (threads 0..103, one group each) ----
    if (tid < NHALO) {
        int er, ec;
        if (tid < 36)       { er = tid / EW;               ec = tid % EW; }
        else if (tid < 72)  { int v = tid - 36; er = EH - 2 + v / EW; ec = v % EW; }
        else if (tid < 88)  { er = 2 + (tid - 72);         ec = 0; }
        else                { er = 2 + (tid - 88);         ec = EW - 1; }
        int gh = row0 - 2 + er;
        int gg = g0 - 1 + ec;
        float out[4] = {0.f, 0.f, 0.f, 0.f};
        if (gh >= 0 && gh < HH && gg >= 0 && gg < GPR) {
            uint4 hrec[9];
            int hg = b * (PLANE / 4) + gh * GPR + gg;
#pragma unroll
            for (int j = 0; j < 9; j++)
                hrec[j] = __ldcg(&wrec[widx(hg, j)]);
            compute_group(xbm, gh, gg, hrec, out);
        }
        *(float4*)&xmid[er * SP + ec * 4] =
            make_float4(out[0], out[1], out[2], out[3]);
    }

    // ---- stage 1b: own group (rec kept in registers for stage 2) ----
    int gh = row0 + ty;
    int gg = g0 + tx;
    uint4 rec[9];
    {
        int g = b * (PLANE / 4) + gh * GPR + gg;
#pragma unroll
        for (int j = 0; j < 9; j++)
            rec[j] = __ldcg(&wrec[widx(g, j)]);
    }
    {
        float out[4] = {0.f, 0.f, 0.f, 0.f};
        compute_group(xbm, gh, gg, rec, out);
        *(float4*)&xmid[(ty + 2) * SP + (tx + 1) * 4] =
            make_float4(out[0], out[1], out[2], out[3]);
    }

    __syncthreads();

    // ---- stage 2: iter k+1 for the own group from smem ----
    // Own group at smem row ty+2, px (tx+1)*4; window = smem rows ty..ty+4,
    // px cols tx*4 .. tx*4+11 (stage 1 wrote zeros outside the image =
    // correct zero padding).
    float acc[4] = {0.f, 0.f, 0.f, 0.f};
#pragma unroll
    for (int r = 0; r < 5; r++) {
        const float* rp = &xmid[(ty + r) * SP + tx * 4];
        float4 v0 = *(const float4*)rp;
        float4 v1 = *(const float4*)(rp + 4);
        float4 v2 = *(const float4*)(rp + 8);
        float xr[12] = {v0.x, v0.y, v0.z, v0.w,
                        v1.x, v1.y, v1.z, v1.w,
                        v2.x, v2.y, v2.z, v2.w};
        apply_row(r, xr, rec, acc);
    }

    *(float4*)(xout + b * PLANE + gh * WW + gg * 4) =
        make_float4(acc[0], acc[1], acc[2], acc[3]);
}

// ---------------------------------------------------------------------------
// Launcher: prep, then 4 fused double-iterations (8 total).
// ---------------------------------------------------------------------------
extern "C" void kernel_launch(void* const* d_in, const int* in_sizes, int n_in,
                              void* d_out, int out_size)
{
    const float* g1 = (const float*)d_in[0];
    const float* g2 = (const float*)d_in[1];
    const float* fu = (const float*)d_in[2];
    const float* x0 = (const float*)d_in[3];
    float* out = (float*)d_out;

    uint4* wrec;
    float *xa, *xb;
    cudaGetSymbolAddress((void**)&wrec, g_wrec);
    cudaGetSymbolAddress((void**)&xa, g_xa);
    cudaGetSymbolAddress((void**)&xb, g_xb);

    prep_kernel<<<2 * NGRP / 512, 512>>>(g1, g2, fu, wrec);

    dim3 pblk(TW, TH, 1);
    dim3 pgrd(GPR / TW, HH / TH, BB);     // (19, 22, 4)
    prop2_kernel<<<pgrd, pblk>>>(x0, wrec, xa);
    prop2_kernel<<<pgrd, pblk>>>(xa, wrec, xb);
    prop2_kernel<<<pgrd, pblk>>>(xb, wrec, xa);
    prop2_kernel<<<pgrd, pblk>>>(xa, wrec, out);
}

// round 8
// speedup vs baseline: 1.3566x; 1.3515x over previous
#include <cuda_runtime.h>
#include <cuda_fp16.h>

// Problem constants (fixed shapes per reference setup_inputs)
#define BB    4
#define HH    352            // rows; 352 = 16 * 22
#define WW    1216           // cols; 1216 = 4 * 304, 304 = 16 * 19
#define PLANE (HH * WW)      // 428032
#define NPIX  (BB * PLANE)   // 1712128
#define NGRP  (NPIX / 4)     // 428032  (4-px groups), PLANE/4 = 107008
#define GPR   304            // groups per row

// Weight records: one 144-B record per 4-px group = 9 x uint4.
// uint4 j = { w1 px01, w2 px01, w1 px23, w2 px23 } (each 2 halves).
// Tap-major swizzle in 32-group blocks over the CANONICAL flat group id
//   g = b*(PLANE/4) + h*304 + gw :   idx(g,j) = (g>>5)*288 + j*32 + (g&31)
__device__ uint4 g_wrec[(size_t)NGRP * 9];   // 61.6 MB
__device__ float g_xa[NPIX];                 // 6.85 MB
__device__ float g_xb[NPIX];                 // 6.85 MB

static __device__ __forceinline__ size_t widx(int g, int j) {
    return (size_t)(g >> 5) * 288 + j * 32 + (g & 31);
}

// Load one zero-padded x row segment: cols w0-4 .. w0+7 of image row hh.
static __device__ __forceinline__ void load_row(
    const float* __restrict__ xbm, int hh, int w0, float xr[12])
{
    bool rok = (hh >= 0) && (hh < HH);
    const float* rowp = xbm + hh * WW;
#pragma unroll
    for (int q = 0; q < 3; q++) {
        int c0 = w0 + (q - 1) * 4;
        float4 v = make_float4(0.f, 0.f, 0.f, 0.f);
        if (rok && c0 >= 0 && c0 < WW)
            v = *(const float4*)(rowp + c0);
        xr[q * 4 + 0] = v.x;
        xr[q * 4 + 1] = v.y;
        xr[q * 4 + 2] = v.z;
        xr[q * 4 + 3] = v.w;
    }
}

// Dilation-1 contributions of one kernel row (3 taps R0..R2) applied to a
// window row. Window cols 0..11 = px w0-4 .. w0+7; output px i center 4+i.
static __device__ __forceinline__ void d1_row(
    const float xr[12], uint4 R0, uint4 R1, uint4 R2, float acc[4])
{
    const uint4 R[3] = {R0, R1, R2};
#pragma unroll
    for (int dc = 0; dc < 3; dc++) {
        float2 a01 = __half22float2(*(const __half2*)&R[dc].x);
        float2 a23 = __half22float2(*(const __half2*)&R[dc].z);
        acc[0] += a01.x * xr[3 + dc];
        acc[1] += a01.y * xr[4 + dc];
        acc[2] += a23.x * xr[5 + dc];
        acc[3] += a23.y * xr[6 + dc];
    }
}

// Dilation-2 contributions of one kernel row (3 taps R0..R2).
static __device__ __forceinline__ void d2_row(
    const float xr[12], uint4 R0, uint4 R1, uint4 R2, float acc[4])
{
    const uint4 R[3] = {R0, R1, R2};
#pragma unroll
    for (int dc = 0; dc < 3; dc++) {
        float2 b01 = __half22float2(*(const __half2*)&R[dc].y);
        float2 b23 = __half22float2(*(const __half2*)&R[dc].w);
        acc[0] += b01.x * xr[2 + 2 * dc];
        acc[1] += b01.y * xr[3 + 2 * dc];
        acc[2] += b23.x * xr[4 + 2 * dc];
        acc[3] += b23.y * xr[5 + 2 * dc];
    }
}

// ---------------------------------------------------------------------------
// prep: per-pixel 9-way softmax of guided1/guided2, scaled by fuse channels.
// Flat 1D: thread u handles 2 px = half of record g = u>>1. Grid exact.
// ---------------------------------------------------------------------------
__global__ __launch_bounds__(512) void prep_kernel(
    const float* __restrict__ g1,
    const float* __restrict__ g2,
    const float* __restrict__ fu,
    uint4* __restrict__ wrec)
{
    int u  = blockIdx.x * 512 + threadIdx.x;   // < 2*NGRP
    int g  = u >> 1;
    int tz = u & 1;
    int px = g * 4 + tz * 2;                   // flat pixel over (b,h,w)
    int b  = px / PLANE;
    int hw = px - b * PLANE;
    int base9 = b * 9 * PLANE + hw;
    int base2 = b * 2 * PLANE + hw;

    float a[9][2], c[9][2];
#pragma unroll
    for (int t = 0; t < 9; t++) {
        *(float2*)a[t] = *(const float2*)(g1 + base9 + t * PLANE);
        *(float2*)c[t] = *(const float2*)(g2 + base9 + t * PLANE);
    }
    float2 f1v = *(const float2*)(fu + base2);
    float2 f2v = *(const float2*)(fu + base2 + PLANE);
    float f1a[2] = {f1v.x, f1v.y};
    float f2a[2] = {f2v.x, f2v.y};

#pragma unroll
    for (int i = 0; i < 2; i++) {
        float m1 = a[0][i], m2 = c[0][i];
#pragma unroll
        for (int t = 1; t < 9; t++) {
            m1 = fmaxf(m1, a[t][i]);
            m2 = fmaxf(m2, c[t][i]);
        }
        float s1 = 0.f, s2 = 0.f;
#pragma unroll
        for (int t = 0; t < 9; t++) {
            float e1 = __expf(a[t][i] - m1); a[t][i] = e1; s1 += e1;
            float e2 = __expf(c[t][i] - m2); c[t][i] = e2; s2 += e2;
        }
        float r1 = f1a[i] / s1;
        float r2 = f2a[i] / s2;
#pragma unroll
        for (int t = 0; t < 9; t++) { a[t][i] *= r1; c[t][i] *= r2; }
    }

#pragma unroll
    for (int j = 0; j < 9; j++) {
        __half2 hw1 = __floats2half2_rn(a[j][0], a[j][1]);
        __half2 hw2 = __floats2half2_rn(c[j][0], c[j][1]);
        uint2 uu;
        uu.x = *(const unsigned int*)&hw1;
        uu.y = *(const unsigned int*)&hw2;
        ((uint2*)&wrec[widx(g, j)])[tz] = uu;
    }
}

// ---------------------------------------------------------------------------
// prop: one propagation iteration; each thread computes TWO vertically
// adjacent 4-px groups (rows gh, gh+1), streaming the 6 shared window rows.
// Weight uint4s are loaded at the first window row that needs them and held
// at most one row (<=6 live), so each record is one LDG.128.
// LSU ops/thread: 18 x-loads + 18 w-loads + 2 stores (vs 30+18+2 naive).
// ---------------------------------------------------------------------------
__global__ __launch_bounds__(128, 6) void prop_kernel(
    const float* __restrict__ xin,
    const uint4* __restrict__ wrec,
    float* __restrict__ xout)
{
    int tx = threadIdx.x;              // 0..15 group-in-tile
    int ty = threadIdx.y;              // 0..7  row-pair-in-tile
    int bx = blockIdx.x, by = blockIdx.y, b = blockIdx.z;
    int gg = bx * 16 + tx;
    int gh = by * 16 + ty * 2;         // group A row; group B = gh+1
    int w0 = gg * 4;
    const float* xbm = xin + b * PLANE;

    int gA = b * (PLANE / 4) + gh * GPR + gg;
    int gB = gA + GPR;
    const uint4* wA = wrec + (size_t)(gA >> 5) * 288 + (gA & 31);
    const uint4* wB = wrec + (size_t)(gB >> 5) * 288 + (gB & 31);

    float accA[4] = {0.f, 0.f, 0.f, 0.f};
    float accB[4] = {0.f, 0.f, 0.f, 0.f};
    uint4 A0, A1, A2, B0, B1, B2;
    float xr[12];

    // Stream window rows gh-2 .. gh+3. A's window rows = wr, B's = wr-1.
    // wr=0: A row0 (d2, dr=0)
    load_row(xbm, gh - 2, w0, xr);
    A0 = __ldcg(wA + 0); A1 = __ldcg(wA + 32); A2 = __ldcg(wA + 64);
    d2_row(xr, A0, A1, A2, accA);

    // wr=1: A row1 (d1, dr=0) ; B row0 (d2, dr=0)
    load_row(xbm, gh - 1, w0, xr);
    d1_row(xr, A0, A1, A2, accA);
    B0 = __ldcg(wB + 0); B1 = __ldcg(wB + 32); B2 = __ldcg(wB + 64);
    d2_row(xr, B0, B1, B2, accB);

    // wr=2: A row2 (d1+d2, dr=1) ; B row1 (d1, dr=0)
    load_row(xbm, gh, w0, xr);
    A0 = __ldcg(wA + 96); A1 = __ldcg(wA + 128); A2 = __ldcg(wA + 160);
    d1_row(xr, A0, A1, A2, accA);
    d2_row(xr, A0, A1, A2, accA);
    d1_row(xr, B0, B1, B2, accB);

    // wr=3: A row3 (d1, dr=2) ; B row2 (d1+d2, dr=1)
    load_row(xbm, gh + 1, w0, xr);
    A0 = __ldcg(wA + 192); A1 = __ldcg(wA + 224); A2 = __ldcg(wA + 256);
    d1_row(xr, A0, A1, A2, accA);
    B0 = __ldcg(wB + 96); B1 = __ldcg(wB + 128); B2 = __ldcg(wB + 160);
    d1_row(xr, B0, B1, B2, accB);
    d2_row(xr, B0, B1, B2, accB);

    // wr=4: A row4 (d2, dr=2) ; B row3 (d1, dr=2)
    load_row(xbm, gh + 2, w0, xr);
    d2_row(xr, A0, A1, A2, accA);
    B0 = __ldcg(wB + 192); B1 = __ldcg(wB + 224); B2 = __ldcg(wB + 256);
    d1_row(xr, B0, B1, B2, accB);

    // wr=5: B row4 (d2, dr=2)
    load_row(xbm, gh + 3, w0, xr);
    d2_row(xr, B0, B1, B2, accB);

    float* op = xout + b * PLANE + gh * WW + w0;
    *(float4*)op        = make_float4(accA[0], accA[1], accA[2], accA[3]);
    *(float4*)(op + WW) = make_float4(accB[0], accB[1], accB[2], accB[3]);
}

// ---------------------------------------------------------------------------
// Launcher: prep, then 8 propagation iterations (L2-resident fp16 records).
// ---------------------------------------------------------------------------
extern "C" void kernel_launch(void* const* d_in, const int* in_sizes, int n_in,
                              void* d_out, int out_size)
{
    const float* g1 = (const float*)d_in[0];
    const float* g2 = (const float*)d_in[1];
    const float* fu = (const float*)d_in[2];
    const float* x0 = (const float*)d_in[3];
    float* out = (float*)d_out;

    uint4* wrec;
    float *xa, *xb;
    cudaGetSymbolAddress((void**)&wrec, g_wrec);
    cudaGetSymbolAddress((void**)&xa, g_xa);
    cudaGetSymbolAddress((void**)&xb, g_xb);

    prep_kernel<<<2 * NGRP / 512, 512>>>(g1, g2, fu, wrec);

    dim3 pblk(16, 8, 1);
    dim3 pgrd(GPR / 16, HH / 16, BB);     // (19, 22, 4)
    const float* src = x0;
    float* dsts[8] = {xa, xb, xa, xb, xa, xb, xa, out};
    for (int i = 0; i < 8; i++) {
        prop_kernel<<<pgrd, pblk>>>(src, wrec, dsts[i]);
        src = dsts[i];
    }
}